// round 4
// baseline (speedup 1.0000x reference)
#include <cuda_runtime.h>
#include <cuda_bf16.h>
#include <cstdint>

// OnlineHadamard, round 4: warp-specialized producer(FHT)/consumer(HMMA) overlap.
//   warps 0-10 : GEMM out[j][m] = sum_k had[j][k]*y[k][m]  (bf16 3-pass, fp32 acc)
//   warps 11-15: FHT64 butterfly of next row -> B buffer (hi/lo bf16)
// Double-buffered B; A (had hi|lo) resident in smem, built once.

#define KDIM 172
#define MDIM 64
#define NROW 11008
#define NT 512

#define ASTR 720                    // A row: [hi 352B | lo 352B] pad to 720 (20w mod 32)
#define BSTR 272                    // B row: [hi 128B | lo 128B] pad to 272 (4w mod 32)
#define A_BYTES (176 * ASTR)        // 126720
#define B_BYTES (176 * BSTR)        // 47872 per buffer
#define OFF_B0  (A_BYTES)
#define OFF_B1  (A_BYTES + B_BYTES)
#define SMEM_DYN (A_BYTES + 2 * B_BYTES)   // 222464

__device__ __forceinline__ uint32_t smem_u32(const void* p) {
    uint32_t a;
    asm("{ .reg .u64 t; cvta.to.shared.u64 t, %1; cvt.u32.u64 %0, t; }" : "=r"(a) : "l"(p));
    return a;
}
__device__ __forceinline__ void ldsm_x4(uint32_t* r, uint32_t addr) {
    asm volatile("ldmatrix.sync.aligned.m8n8.x4.shared.b16 {%0,%1,%2,%3}, [%4];"
                 : "=r"(r[0]), "=r"(r[1]), "=r"(r[2]), "=r"(r[3]) : "r"(addr));
}
__device__ __forceinline__ void ldsm_x4t(uint32_t* r, uint32_t addr) {
    asm volatile("ldmatrix.sync.aligned.m8n8.x4.trans.shared.b16 {%0,%1,%2,%3}, [%4];"
                 : "=r"(r[0]), "=r"(r[1]), "=r"(r[2]), "=r"(r[3]) : "r"(addr));
}
__device__ __forceinline__ void mma_bf16(float* c, const uint32_t* a, uint32_t b0, uint32_t b1) {
    asm volatile("mma.sync.aligned.m16n8k16.row.col.f32.bf16.bf16.f32 "
                 "{%0,%1,%2,%3}, {%4,%5,%6,%7}, {%8,%9}, {%0,%1,%2,%3};"
                 : "+f"(c[0]), "+f"(c[1]), "+f"(c[2]), "+f"(c[3])
                 : "r"(a[0]), "r"(a[1]), "r"(a[2]), "r"(a[3]), "r"(b0), "r"(b1));
}

// FHT one row of x into B buffer (hi|lo bf16 per smem row), warps wp of NP producers
__device__ __forceinline__ void fht_row(const float* __restrict__ xr, char* bbuf,
                                        int lane, int wp, int np, float scale) {
    for (int c = wp; c < KDIM; c += np) {
        float2 v = *(const float2*)(xr + (c << 6) + 2 * lane);
        float p0 = v.x + v.y, p1 = v.x - v.y;
        #pragma unroll
        for (int s = 0; s < 5; s++) {
            int m = 1 << s;
            float q0 = __shfl_xor_sync(0xffffffffu, p0, m);
            float q1 = __shfl_xor_sync(0xffffffffu, p1, m);
            if (lane & m) { p0 = q0 - p0; p1 = q1 - p1; }
            else          { p0 = p0 + q0; p1 = p1 + q1; }
        }
        p0 *= scale; p1 *= scale;
        __nv_bfloat16 h0 = __float2bfloat16(p0), h1 = __float2bfloat16(p1);
        float r0 = p0 - __bfloat162float(h0), r1 = p1 - __bfloat162float(h1);
        __nv_bfloat162 hp = __halves2bfloat162(h0, h1);
        __nv_bfloat162 lp = __halves2bfloat162(__float2bfloat16(r0), __float2bfloat16(r1));
        *(uint32_t*)(bbuf + c * BSTR + lane * 4)       = *(uint32_t*)&hp;
        *(uint32_t*)(bbuf + c * BSTR + 128 + lane * 4) = *(uint32_t*)&lp;
    }
}

__global__ __launch_bounds__(NT, 1)
void onl_had_ws_kernel(const float* __restrict__ x,
                       const float* __restrict__ had,
                       float* __restrict__ out, int rows)
{
    extern __shared__ char sm[];
    const uint32_t sbase = smem_u32(sm);
    const int tid = threadIdx.x, lane = tid & 31, warp = tid >> 5;

    // ---- one-time: A = had (hi|lo bf16), zero-padded to 176x176 ----
    for (int idx = tid; idx < 176 * 176; idx += NT) {
        int j = idx / 176, k = idx - j * 176;
        float v = (j < KDIM && k < KDIM) ? had[j * KDIM + k] : 0.0f;
        __nv_bfloat16 h = __float2bfloat16(v);
        __nv_bfloat16 l = __float2bfloat16(v - __bfloat162float(h));
        *(__nv_bfloat16*)(sm + j * ASTR + 2 * k)       = h;
        *(__nv_bfloat16*)(sm + j * ASTR + 352 + 2 * k) = l;
    }
    // zero B pad rows k=172..175 in both buffers (64 halves hi + 64 lo per row)
    for (int idx = tid; idx < 2 * 4 * 64; idx += NT) {
        int b = idx >> 8, r = (idx >> 6) & 3, m = idx & 63;
        char* p = sm + (b ? OFF_B1 : OFF_B0) + (172 + r) * BSTR;
        *(__nv_bfloat16*)(p + 2 * m)       = __float2bfloat16(0.0f);
        *(__nv_bfloat16*)(p + 128 + 2 * m) = __float2bfloat16(0.0f);
    }
    __syncthreads();

    const float scale = rsqrtf((float)NROW);
    const int stride = gridDim.x;

    // consumer addressing (warps 0..10)
    const int jt = warp;
    uint32_t a_addr = sbase + (uint32_t)(jt * 16 + (lane & 7) + ((lane >> 3) & 1) * 8) * ASTR
                    + (uint32_t)((lane >> 4) * 16);
    // B x4 trans: lanes 0-15 rows k (lane&15); lanes 16-31 same rows, col +16B (next mt)
    uint32_t b_lane_off = (uint32_t)((lane & 15) * BSTR + (lane >> 4) * 16);
    const int eq = lane & 3, er = lane >> 2;
    const int j1 = jt * 16 + er, j2 = j1 + 8;

    // prologue: producers build B for first row
    int row0 = blockIdx.x;
    if (row0 < rows && warp >= 11)
        fht_row(x + (size_t)row0 * NROW, sm + OFF_B0, lane, warp - 11, 5, scale);
    __syncthreads();

    int buf = 0;
    for (int row = row0; row < rows; row += stride) {
        int nxt = row + stride;
        if (warp < 11) {
            // ---------------- consumer: GEMM + store ----------------
            uint32_t bbase = sbase + (buf ? OFF_B1 : OFF_B0) + b_lane_off;
            float acc[8][4];
            #pragma unroll
            for (int mt = 0; mt < 8; mt++)
                acc[mt][0] = acc[mt][1] = acc[mt][2] = acc[mt][3] = 0.f;

            for (int kt = 0; kt < 11; kt++) {
                uint32_t ah[4], al[4];
                ldsm_x4(ah, a_addr + kt * 32);
                ldsm_x4(al, a_addr + 352 + kt * 32);
                uint32_t bk = bbase + (uint32_t)(kt * 16 * BSTR);
                #pragma unroll
                for (int mt2 = 0; mt2 < 4; mt2++) {
                    uint32_t bh[4], bl[4];
                    ldsm_x4t(bh, bk + mt2 * 32);
                    ldsm_x4t(bl, bk + 128 + mt2 * 32);
                    mma_bf16(acc[2 * mt2],     ah, bh[0], bh[1]);
                    mma_bf16(acc[2 * mt2],     ah, bl[0], bl[1]);
                    mma_bf16(acc[2 * mt2],     al, bh[0], bh[1]);
                    mma_bf16(acc[2 * mt2 + 1], ah, bh[2], bh[3]);
                    mma_bf16(acc[2 * mt2 + 1], ah, bl[2], bl[3]);
                    mma_bf16(acc[2 * mt2 + 1], al, bh[2], bh[3]);
                }
            }
            float* orow = out + (size_t)row * NROW;
            if (j1 < KDIM) {
                float* o1 = orow + j1 * MDIM + eq * 2;
                #pragma unroll
                for (int mt = 0; mt < 8; mt++)
                    *(float2*)(o1 + mt * 8) = make_float2(acc[mt][0], acc[mt][1]);
            }
            if (j2 < KDIM) {
                float* o2 = orow + j2 * MDIM + eq * 2;
                #pragma unroll
                for (int mt = 0; mt < 8; mt++)
                    *(float2*)(o2 + mt * 8) = make_float2(acc[mt][2], acc[mt][3]);
            }
        } else if (nxt < rows) {
            // ---------------- producer: FHT next row into other buffer ----------------
            fht_row(x + (size_t)nxt * NROW, sm + (buf ? OFF_B0 : OFF_B1),
                    lane, warp - 11, 5, scale);
        }
        buf ^= 1;
        __syncthreads();
    }
}

extern "C" void kernel_launch(void* const* d_in, const int* in_sizes, int n_in,
                              void* d_out, int out_size) {
    const float* x   = (const float*)d_in[0];
    const float* had = (const float*)d_in[1];
    float* out = (float*)d_out;
    int rows = in_sizes[0] / NROW;

    cudaFuncSetAttribute(onl_had_ws_kernel,
                         cudaFuncAttributeMaxDynamicSharedMemorySize, SMEM_DYN);
    int grid = rows < 152 ? rows : 152;
    onl_had_ws_kernel<<<grid, NT, SMEM_DYN>>>(x, had, out, rows);
}

// round 5
// speedup vs baseline: 3.2409x; 3.2409x over previous
#include <cuda_runtime.h>
#include <cuda_bf16.h>
#include <cstdint>

// OnlineHadamard round 5: single-barrier pipelined rows.
//  warps 0-10: prefetch(6 LDG row i+1) -> GEMM(row i) -> butterfly own 6 chunks
//  warps 11-15: load+butterfly 21-22 chunks of row i+1 (overlaps GEMM)
// B double-buffered; A (had hi|lo bf16) resident; 3-pass bf16 HMMA, fp32 accum.

#define KDIM 172
#define MDIM 64
#define NROW 11008
#define NT 512

#define ASTR 720                    // A row: [hi 352B | lo 352B] pad->720
#define BSTR 272                    // B row: [hi 128B | lo 128B] pad->272
#define A_BYTES (176 * ASTR)
#define B_BYTES (176 * BSTR)
#define OFF_B0  (A_BYTES)
#define OFF_B1  (A_BYTES + B_BYTES)
#define SMEM_DYN (A_BYTES + 2 * B_BYTES)   // 222464

__device__ __forceinline__ uint32_t smem_u32(const void* p) {
    uint32_t a;
    asm("{ .reg .u64 t; cvta.to.shared.u64 t, %1; cvt.u32.u64 %0, t; }" : "=r"(a) : "l"(p));
    return a;
}
__device__ __forceinline__ void ldsm_x4(uint32_t* r, uint32_t addr) {
    asm volatile("ldmatrix.sync.aligned.m8n8.x4.shared.b16 {%0,%1,%2,%3}, [%4];"
                 : "=r"(r[0]), "=r"(r[1]), "=r"(r[2]), "=r"(r[3]) : "r"(addr));
}
__device__ __forceinline__ void ldsm_x4t(uint32_t* r, uint32_t addr) {
    asm volatile("ldmatrix.sync.aligned.m8n8.x4.trans.shared.b16 {%0,%1,%2,%3}, [%4];"
                 : "=r"(r[0]), "=r"(r[1]), "=r"(r[2]), "=r"(r[3]) : "r"(addr));
}
__device__ __forceinline__ void mma_bf16(float* c, const uint32_t* a, uint32_t b0, uint32_t b1) {
    asm volatile("mma.sync.aligned.m16n8k16.row.col.f32.bf16.bf16.f32 "
                 "{%0,%1,%2,%3}, {%4,%5,%6,%7}, {%8,%9}, {%0,%1,%2,%3};"
                 : "+f"(c[0]), "+f"(c[1]), "+f"(c[2]), "+f"(c[3])
                 : "r"(a[0]), "r"(a[1]), "r"(a[2]), "r"(a[3]), "r"(b0), "r"(b1));
}

// butterfly one loaded chunk and store hi/lo bf16 into B row c
__device__ __forceinline__ void bfly_store(float2 v, char* bbuf, int c, int lane, float scale) {
    float p0 = v.x + v.y, p1 = v.x - v.y;
    #pragma unroll
    for (int s = 0; s < 5; s++) {
        int m = 1 << s;
        float q0 = __shfl_xor_sync(0xffffffffu, p0, m);
        float q1 = __shfl_xor_sync(0xffffffffu, p1, m);
        if (lane & m) { p0 = q0 - p0; p1 = q1 - p1; }
        else          { p0 = p0 + q0; p1 = p1 + q1; }
    }
    p0 *= scale; p1 *= scale;
    __nv_bfloat16 h0 = __float2bfloat16(p0), h1 = __float2bfloat16(p1);
    float r0 = p0 - __bfloat162float(h0), r1 = p1 - __bfloat162float(h1);
    __nv_bfloat162 hp = __halves2bfloat162(h0, h1);
    __nv_bfloat162 lp = __halves2bfloat162(__float2bfloat16(r0), __float2bfloat16(r1));
    *(uint32_t*)(bbuf + c * BSTR + lane * 4)       = *(uint32_t*)&hp;
    *(uint32_t*)(bbuf + c * BSTR + 128 + lane * 4) = *(uint32_t*)&lp;
}

__global__ __launch_bounds__(NT, 1)
void onl_had_r5_kernel(const float* __restrict__ x,
                       const float* __restrict__ had,
                       float* __restrict__ out, int rows)
{
    extern __shared__ char sm[];
    const uint32_t sbase = smem_u32(sm);
    const int tid = threadIdx.x, lane = tid & 31, warp = tid >> 5;

    // ---- one-time: A = had (hi|lo bf16), zero-padded to 176x176 ----
    for (int idx = tid; idx < 176 * 176; idx += NT) {
        int j = idx / 176, k = idx - j * 176;
        float v = (j < KDIM && k < KDIM) ? had[j * KDIM + k] : 0.0f;
        __nv_bfloat16 h = __float2bfloat16(v);
        __nv_bfloat16 l = __float2bfloat16(v - __bfloat162float(h));
        *(__nv_bfloat16*)(sm + j * ASTR + 2 * k)       = h;
        *(__nv_bfloat16*)(sm + j * ASTR + 352 + 2 * k) = l;
    }
    // zero B pad rows 172..175, both buffers
    for (int idx = tid; idx < 2 * 4 * 64; idx += NT) {
        int b = idx >> 8, r = (idx >> 6) & 3, m = idx & 63;
        char* p = sm + (b ? OFF_B1 : OFF_B0) + (172 + r) * BSTR;
        *(__nv_bfloat16*)(p + 2 * m)       = __float2bfloat16(0.0f);
        *(__nv_bfloat16*)(p + 128 + 2 * m) = __float2bfloat16(0.0f);
    }

    const float scale = rsqrtf((float)NROW);
    const int stride = gridDim.x;

    // GEMM addressing (warps 0..10)
    const int jt = warp;
    uint32_t a_addr = sbase + (uint32_t)(jt * 16 + (lane & 7) + ((lane >> 3) & 1) * 8) * ASTR
                    + (uint32_t)((lane >> 4) * 16);
    uint32_t b_lane_off = (uint32_t)((lane & 15) * BSTR + (lane >> 4) * 16);
    const int eq = lane & 3, er = lane >> 2;
    const int j1 = jt * 16 + er, j2 = j1 + 8;

    // FHT chunk bases: gemm warp w -> c = w + 11t (t<6); helper w -> c = 66+(w-11)+5t
    const int hbase = 66 + (warp - 11);

    // ---- prologue: all warps butterfly row0 into B0 ----
    int row0 = blockIdx.x;
    if (row0 < rows) {
        const float* xr = x + (size_t)row0 * NROW;
        if (warp < 11) {
            #pragma unroll
            for (int t = 0; t < 6; t++) {
                int c = warp + 11 * t;
                bfly_store(*(const float2*)(xr + (c << 6) + 2 * lane), sm + OFF_B0, c, lane, scale);
            }
        } else {
            #pragma unroll
            for (int t = 0; t < 22; t++) {
                int c = hbase + 5 * t;
                if (c < KDIM)
                    bfly_store(*(const float2*)(xr + (c << 6) + 2 * lane), sm + OFF_B0, c, lane, scale);
            }
        }
    }
    __syncthreads();

    int buf = 0;
    for (int row = row0; row < rows; row += stride) {
        const int nxt = row + stride;
        const bool have_nxt = nxt < rows;
        char* bnext = sm + (buf ? OFF_B0 : OFF_B1);

        if (warp < 11) {
            // -- issue prefetch LDGs for next row (overlap with GEMM below) --
            float2 pf[6];
            if (have_nxt) {
                const float* xn = x + (size_t)nxt * NROW;
                #pragma unroll
                for (int t = 0; t < 6; t++)
                    pf[t] = *(const float2*)(xn + ((warp + 11 * t) << 6) + 2 * lane);
            }
            // -------- GEMM row i --------
            uint32_t bbase = sbase + (buf ? OFF_B1 : OFF_B0) + b_lane_off;
            float acc[8][4];
            #pragma unroll
            for (int mt = 0; mt < 8; mt++)
                acc[mt][0] = acc[mt][1] = acc[mt][2] = acc[mt][3] = 0.f;

            for (int kt = 0; kt < 11; kt++) {
                uint32_t ah[4], al[4];
                ldsm_x4(ah, a_addr + kt * 32);
                ldsm_x4(al, a_addr + 352 + kt * 32);
                uint32_t bk = bbase + (uint32_t)(kt * 16 * BSTR);
                #pragma unroll
                for (int mt2 = 0; mt2 < 4; mt2++) {
                    uint32_t bh[4], bl[4];
                    ldsm_x4t(bh, bk + mt2 * 32);
                    ldsm_x4t(bl, bk + 128 + mt2 * 32);
                    mma_bf16(acc[2 * mt2],     ah, bh[0], bh[1]);
                    mma_bf16(acc[2 * mt2],     ah, bl[0], bl[1]);
                    mma_bf16(acc[2 * mt2],     al, bh[0], bh[1]);
                    mma_bf16(acc[2 * mt2 + 1], ah, bh[2], bh[3]);
                    mma_bf16(acc[2 * mt2 + 1], ah, bl[2], bl[3]);
                    mma_bf16(acc[2 * mt2 + 1], al, bh[2], bh[3]);
                }
            }
            float* orow = out + (size_t)row * NROW;
            if (j1 < KDIM) {
                float* o1 = orow + j1 * MDIM + eq * 2;
                #pragma unroll
                for (int mt = 0; mt < 8; mt++)
                    *(float2*)(o1 + mt * 8) = make_float2(acc[mt][0], acc[mt][1]);
            }
            if (j2 < KDIM) {
                float* o2 = orow + j2 * MDIM + eq * 2;
                #pragma unroll
                for (int mt = 0; mt < 8; mt++)
                    *(float2*)(o2 + mt * 8) = make_float2(acc[mt][2], acc[mt][3]);
            }
            // -- butterfly own chunks of next row from prefetched regs --
            if (have_nxt) {
                #pragma unroll
                for (int t = 0; t < 6; t++)
                    bfly_store(pf[t], bnext, warp + 11 * t, lane, scale);
            }
        } else if (have_nxt) {
            // -------- helper: load+butterfly 21-22 chunks of next row --------
            const float* xn = x + (size_t)nxt * NROW;
            float2 pf[22];
            #pragma unroll
            for (int t = 0; t < 22; t++) {
                int c = hbase + 5 * t;
                if (c < KDIM) pf[t] = *(const float2*)(xn + (c << 6) + 2 * lane);
            }
            #pragma unroll
            for (int t = 0; t < 22; t++) {
                int c = hbase + 5 * t;
                if (c < KDIM) bfly_store(pf[t], bnext, c, lane, scale);
            }
        }
        buf ^= 1;
        __syncthreads();
    }
}

extern "C" void kernel_launch(void* const* d_in, const int* in_sizes, int n_in,
                              void* d_out, int out_size) {
    const float* x   = (const float*)d_in[0];
    const float* had = (const float*)d_in[1];
    float* out = (float*)d_out;
    int rows = in_sizes[0] / NROW;

    cudaFuncSetAttribute(onl_had_r5_kernel,
                         cudaFuncAttributeMaxDynamicSharedMemorySize, SMEM_DYN);
    int grid = rows < 152 ? rows : 152;
    onl_had_r5_kernel<<<grid, NT, SMEM_DYN>>>(x, had, out, rows);
}

// round 6
// speedup vs baseline: 4.3987x; 1.3572x over previous
#include <cuda_runtime.h>
#include <cuda_fp16.h>
#include <cstdint>

// OnlineHadamard round 6: fp16 2-pass split (A = Ah+Al fp16, B single fp16).
//  warps 0-10: prefetch(6 LDG row i+1) -> GEMM(row i) -> butterfly own 6 chunks
//  warps 11-15: load+butterfly 21-22 chunks of row i+1 (overlaps GEMM)
// B double-buffered; A (had hi|lo fp16) resident; fp32 accum.

#define KDIM 172
#define MDIM 64
#define NROW 11008
#define NT 512

#define ASTR 720                    // A row: [hi 352B | lo 352B] pad->720 (20w mod 32)
#define BSTR 144                    // B row: 128B fp16 pad->144 (4w mod 32, conflict-free)
#define A_BYTES (176 * ASTR)        // 126720
#define B_BYTES (176 * BSTR)        // 25344 per buffer
#define OFF_B0  (A_BYTES)
#define OFF_B1  (A_BYTES + B_BYTES)
#define SMEM_DYN (A_BYTES + 2 * B_BYTES)   // 177408

__device__ __forceinline__ uint32_t smem_u32(const void* p) {
    uint32_t a;
    asm("{ .reg .u64 t; cvta.to.shared.u64 t, %1; cvt.u32.u64 %0, t; }" : "=r"(a) : "l"(p));
    return a;
}
__device__ __forceinline__ void ldsm_x4(uint32_t* r, uint32_t addr) {
    asm volatile("ldmatrix.sync.aligned.m8n8.x4.shared.b16 {%0,%1,%2,%3}, [%4];"
                 : "=r"(r[0]), "=r"(r[1]), "=r"(r[2]), "=r"(r[3]) : "r"(addr));
}
__device__ __forceinline__ void ldsm_x4t(uint32_t* r, uint32_t addr) {
    asm volatile("ldmatrix.sync.aligned.m8n8.x4.trans.shared.b16 {%0,%1,%2,%3}, [%4];"
                 : "=r"(r[0]), "=r"(r[1]), "=r"(r[2]), "=r"(r[3]) : "r"(addr));
}
__device__ __forceinline__ void mma_f16(float* c, const uint32_t* a, uint32_t b0, uint32_t b1) {
    asm volatile("mma.sync.aligned.m16n8k16.row.col.f32.f16.f16.f32 "
                 "{%0,%1,%2,%3}, {%4,%5,%6,%7}, {%8,%9}, {%0,%1,%2,%3};"
                 : "+f"(c[0]), "+f"(c[1]), "+f"(c[2]), "+f"(c[3])
                 : "r"(a[0]), "r"(a[1]), "r"(a[2]), "r"(a[3]), "r"(b0), "r"(b1));
}

// butterfly one loaded chunk and store fp16 into B row c
__device__ __forceinline__ void bfly_store(float2 v, char* bbuf, int c, int lane, float scale) {
    float p0 = v.x + v.y, p1 = v.x - v.y;
    #pragma unroll
    for (int s = 0; s < 5; s++) {
        int m = 1 << s;
        float q0 = __shfl_xor_sync(0xffffffffu, p0, m);
        float q1 = __shfl_xor_sync(0xffffffffu, p1, m);
        if (lane & m) { p0 = q0 - p0; p1 = q1 - p1; }
        else          { p0 = p0 + q0; p1 = p1 + q1; }
    }
    __half2 hp = __halves2half2(__float2half_rn(p0 * scale), __float2half_rn(p1 * scale));
    *(uint32_t*)(bbuf + c * BSTR + lane * 4) = *(uint32_t*)&hp;
}

__global__ __launch_bounds__(NT, 1)
void onl_had_r6_kernel(const float* __restrict__ x,
                       const float* __restrict__ had,
                       float* __restrict__ out, int rows)
{
    extern __shared__ char sm[];
    const uint32_t sbase = smem_u32(sm);
    const int tid = threadIdx.x, lane = tid & 31, warp = tid >> 5;

    // ---- one-time: A = had (hi|lo fp16), zero-padded to 176x176 ----
    for (int idx = tid; idx < 176 * 176; idx += NT) {
        int j = idx / 176, k = idx - j * 176;
        float v = (j < KDIM && k < KDIM) ? had[j * KDIM + k] : 0.0f;
        __half h = __float2half_rn(v);
        __half l = __float2half_rn(v - __half2float(h));
        *(__half*)(sm + j * ASTR + 2 * k)       = h;
        *(__half*)(sm + j * ASTR + 352 + 2 * k) = l;
    }
    // zero B pad rows 172..175, both buffers
    for (int idx = tid; idx < 2 * 4 * 64; idx += NT) {
        int b = idx >> 8, r = (idx >> 6) & 3, m = idx & 63;
        char* p = sm + (b ? OFF_B1 : OFF_B0) + (172 + r) * BSTR;
        *(__half*)(p + 2 * m) = __float2half_rn(0.0f);
    }

    const float scale = rsqrtf((float)NROW);
    const int stride = gridDim.x;

    // GEMM addressing (warps 0..10)
    const int jt = warp;
    uint32_t a_addr = sbase + (uint32_t)(jt * 16 + (lane & 7) + ((lane >> 3) & 1) * 8) * ASTR
                    + (uint32_t)((lane >> 4) * 16);
    uint32_t b_lane_off = (uint32_t)((lane & 15) * BSTR + (lane >> 4) * 16);
    const int eq = lane & 3, er = lane >> 2;
    const int j1 = jt * 16 + er, j2 = j1 + 8;

    // FHT chunk bases: gemm warp w -> c = w + 11t (t<6); helper w -> c = 66+(w-11)+5t
    const int hbase = 66 + (warp - 11);

    // ---- prologue: all warps butterfly row0 into B0 ----
    int row0 = blockIdx.x;
    if (row0 < rows) {
        const float* xr = x + (size_t)row0 * NROW;
        if (warp < 11) {
            #pragma unroll
            for (int t = 0; t < 6; t++) {
                int c = warp + 11 * t;
                bfly_store(*(const float2*)(xr + (c << 6) + 2 * lane), sm + OFF_B0, c, lane, scale);
            }
        } else {
            #pragma unroll
            for (int t = 0; t < 22; t++) {
                int c = hbase + 5 * t;
                if (c < KDIM)
                    bfly_store(*(const float2*)(xr + (c << 6) + 2 * lane), sm + OFF_B0, c, lane, scale);
            }
        }
    }
    __syncthreads();

    int buf = 0;
    for (int row = row0; row < rows; row += stride) {
        const int nxt = row + stride;
        const bool have_nxt = nxt < rows;
        char* bnext = sm + (buf ? OFF_B0 : OFF_B1);

        if (warp < 11) {
            // -- issue prefetch LDGs for next row (overlap with GEMM below) --
            float2 pf[6];
            if (have_nxt) {
                const float* xn = x + (size_t)nxt * NROW;
                #pragma unroll
                for (int t = 0; t < 6; t++)
                    pf[t] = *(const float2*)(xn + ((warp + 11 * t) << 6) + 2 * lane);
            }
            // -------- GEMM row i (2-pass fp16) --------
            uint32_t bbase = sbase + (buf ? OFF_B1 : OFF_B0) + b_lane_off;
            float acc[8][4];
            #pragma unroll
            for (int mt = 0; mt < 8; mt++)
                acc[mt][0] = acc[mt][1] = acc[mt][2] = acc[mt][3] = 0.f;

            for (int kt = 0; kt < 11; kt++) {
                uint32_t ah[4], al[4];
                ldsm_x4(ah, a_addr + kt * 32);
                ldsm_x4(al, a_addr + 352 + kt * 32);
                uint32_t bk = bbase + (uint32_t)(kt * 16 * BSTR);
                #pragma unroll
                for (int mt2 = 0; mt2 < 4; mt2++) {
                    uint32_t bh[4];
                    ldsm_x4t(bh, bk + mt2 * 32);
                    mma_f16(acc[2 * mt2],     ah, bh[0], bh[1]);
                    mma_f16(acc[2 * mt2],     al, bh[0], bh[1]);
                    mma_f16(acc[2 * mt2 + 1], ah, bh[2], bh[3]);
                    mma_f16(acc[2 * mt2 + 1], al, bh[2], bh[3]);
                }
            }
            float* orow = out + (size_t)row * NROW;
            if (j1 < KDIM) {
                float* o1 = orow + j1 * MDIM + eq * 2;
                #pragma unroll
                for (int mt = 0; mt < 8; mt++)
                    *(float2*)(o1 + mt * 8) = make_float2(acc[mt][0], acc[mt][1]);
            }
            if (j2 < KDIM) {
                float* o2 = orow + j2 * MDIM + eq * 2;
                #pragma unroll
                for (int mt = 0; mt < 8; mt++)
                    *(float2*)(o2 + mt * 8) = make_float2(acc[mt][2], acc[mt][3]);
            }
            // -- butterfly own chunks of next row from prefetched regs --
            if (have_nxt) {
                #pragma unroll
                for (int t = 0; t < 6; t++)
                    bfly_store(pf[t], bnext, warp + 11 * t, lane, scale);
            }
        } else if (have_nxt) {
            // -------- helper: load+butterfly 21-22 chunks of next row --------
            const float* xn = x + (size_t)nxt * NROW;
            float2 pf[22];
            #pragma unroll
            for (int t = 0; t < 22; t++) {
                int c = hbase + 5 * t;
                if (c < KDIM) pf[t] = *(const float2*)(xn + (c << 6) + 2 * lane);
            }
            #pragma unroll
            for (int t = 0; t < 22; t++) {
                int c = hbase + 5 * t;
                if (c < KDIM) bfly_store(pf[t], bnext, c, lane, scale);
            }
        }
        buf ^= 1;
        __syncthreads();
    }
}

extern "C" void kernel_launch(void* const* d_in, const int* in_sizes, int n_in,
                              void* d_out, int out_size) {
    const float* x   = (const float*)d_in[0];
    const float* had = (const float*)d_in[1];
    float* out = (float*)d_out;
    int rows = in_sizes[0] / NROW;

    cudaFuncSetAttribute(onl_had_r6_kernel,
                         cudaFuncAttributeMaxDynamicSharedMemorySize, SMEM_DYN);
    int grid = rows < 152 ? rows : 152;
    onl_had_r6_kernel<<<grid, NT, SMEM_DYN>>>(x, had, out, rows);
}

// round 7
// speedup vs baseline: 5.4205x; 1.2323x over previous
#include <cuda_runtime.h>
#include <cuda_fp16.h>
#include <cstdint>

// OnlineHadamard round 7: single-pass fp16 HMMA, A resident in registers.
//  NT=384. warps 0-10: prefetch(14 LDG) -> GEMM(row i) -> butterfly 14 chunks
//          warp 11:    load+butterfly 18 chunks of row i+1 (overlaps GEMM)
// A (had fp16) loaded once into per-warp register fragments; B double-buffered fp16.

#define KDIM 172
#define MDIM 64
#define NROW 11008
#define NT 384

#define ASTR 368                    // A row: 352B fp16 pad->368 (23w mod 32, ldsm-safe)
#define BSTR 144                    // B row: 128B fp16 pad->144
#define A_BYTES (176 * ASTR)        // 64768
#define B_BYTES (176 * BSTR)        // 25344 per buffer
#define OFF_B0  (A_BYTES)
#define OFF_B1  (A_BYTES + B_BYTES)
#define SMEM_DYN (A_BYTES + 2 * B_BYTES)   // 115456

__device__ __forceinline__ uint32_t smem_u32(const void* p) {
    uint32_t a;
    asm("{ .reg .u64 t; cvta.to.shared.u64 t, %1; cvt.u32.u64 %0, t; }" : "=r"(a) : "l"(p));
    return a;
}
__device__ __forceinline__ void ldsm_x4(uint32_t* r, uint32_t addr) {
    asm volatile("ldmatrix.sync.aligned.m8n8.x4.shared.b16 {%0,%1,%2,%3}, [%4];"
                 : "=r"(r[0]), "=r"(r[1]), "=r"(r[2]), "=r"(r[3]) : "r"(addr));
}
__device__ __forceinline__ void ldsm_x4t(uint32_t* r, uint32_t addr) {
    asm volatile("ldmatrix.sync.aligned.m8n8.x4.trans.shared.b16 {%0,%1,%2,%3}, [%4];"
                 : "=r"(r[0]), "=r"(r[1]), "=r"(r[2]), "=r"(r[3]) : "r"(addr));
}
__device__ __forceinline__ void mma_f16(float* c, const uint32_t* a, uint32_t b0, uint32_t b1) {
    asm volatile("mma.sync.aligned.m16n8k16.row.col.f32.f16.f16.f32 "
                 "{%0,%1,%2,%3}, {%4,%5,%6,%7}, {%8,%9}, {%0,%1,%2,%3};"
                 : "+f"(c[0]), "+f"(c[1]), "+f"(c[2]), "+f"(c[3])
                 : "r"(a[0]), "r"(a[1]), "r"(a[2]), "r"(a[3]), "r"(b0), "r"(b1));
}

__device__ __forceinline__ void bfly_store(float2 v, char* bbuf, int c, int lane, float scale) {
    float p0 = v.x + v.y, p1 = v.x - v.y;
    #pragma unroll
    for (int s = 0; s < 5; s++) {
        int m = 1 << s;
        float q0 = __shfl_xor_sync(0xffffffffu, p0, m);
        float q1 = __shfl_xor_sync(0xffffffffu, p1, m);
        if (lane & m) { p0 = q0 - p0; p1 = q1 - p1; }
        else          { p0 = p0 + q0; p1 = p1 + q1; }
    }
    __half2 hp = __halves2half2(__float2half_rn(p0 * scale), __float2half_rn(p1 * scale));
    *(uint32_t*)(bbuf + c * BSTR + lane * 4) = *(uint32_t*)&hp;
}

__global__ __launch_bounds__(NT, 1)
void onl_had_r7_kernel(const float* __restrict__ x,
                       const float* __restrict__ had,
                       float* __restrict__ out, int rows)
{
    extern __shared__ char sm[];
    const uint32_t sbase = smem_u32(sm);
    const int tid = threadIdx.x, lane = tid & 31, warp = tid >> 5;

    // ---- one-time: A = had (fp16), zero-padded to 176x176 ----
    for (int idx = tid; idx < 176 * 176; idx += NT) {
        int j = idx / 176, k = idx - j * 176;
        float v = (j < KDIM && k < KDIM) ? had[j * KDIM + k] : 0.0f;
        *(__half*)(sm + j * ASTR + 2 * k) = __float2half_rn(v);
    }
    // zero B pad rows 172..175, both buffers
    for (int idx = tid; idx < 2 * 4 * 64; idx += NT) {
        int b = idx >> 8, r = (idx >> 6) & 3, m = idx & 63;
        char* p = sm + (b ? OFF_B1 : OFF_B0) + (172 + r) * BSTR;
        *(__half*)(p + 2 * m) = __float2half_rn(0.0f);
    }
    __syncthreads();

    const float scale = rsqrtf((float)NROW);
    const int stride = gridDim.x;

    // ---- GEMM warps: load A fragments once into registers ----
    const int jt = warp;
    uint32_t a_frag[11][4];
    if (warp < 11) {
        uint32_t a_addr = sbase
            + (uint32_t)(jt * 16 + (lane & 7) + ((lane >> 3) & 1) * 8) * ASTR
            + (uint32_t)((lane >> 4) * 16);
        #pragma unroll
        for (int kt = 0; kt < 11; kt++)
            ldsm_x4(a_frag[kt], a_addr + kt * 32);
    }

    uint32_t b_lane_off = (uint32_t)((lane & 15) * BSTR + (lane >> 4) * 16);
    const int eq = lane & 3, er = lane >> 2;
    const int j1 = jt * 16 + er, j2 = j1 + 8;

    // FHT: gemm warp w -> c = w + 11t (t<14, covers 0..153); warp 11 -> 154..171
    // ---- prologue: all warps butterfly row0 into B0 ----
    int row0 = blockIdx.x;
    if (row0 < rows) {
        const float* xr = x + (size_t)row0 * NROW;
        if (warp < 11) {
            #pragma unroll
            for (int t = 0; t < 14; t++) {
                int c = warp + 11 * t;
                bfly_store(*(const float2*)(xr + (c << 6) + 2 * lane), sm + OFF_B0, c, lane, scale);
            }
        } else {
            #pragma unroll
            for (int t = 0; t < 18; t++) {
                int c = 154 + t;
                bfly_store(*(const float2*)(xr + (c << 6) + 2 * lane), sm + OFF_B0, c, lane, scale);
            }
        }
    }
    __syncthreads();

    int buf = 0;
    for (int row = row0; row < rows; row += stride) {
        const int nxt = row + stride;
        const bool have_nxt = nxt < rows;
        char* bnext = sm + (buf ? OFF_B0 : OFF_B1);

        if (warp < 11) {
            // -- prefetch LDGs for next row (retire under GEMM) --
            float2 pf[14];
            if (have_nxt) {
                const float* xn = x + (size_t)nxt * NROW;
                #pragma unroll
                for (int t = 0; t < 14; t++)
                    pf[t] = *(const float2*)(xn + ((warp + 11 * t) << 6) + 2 * lane);
            }
            // -------- GEMM row i (single-pass fp16, A in regs) --------
            uint32_t bbase = sbase + (buf ? OFF_B1 : OFF_B0) + b_lane_off;
            float acc[8][4];
            #pragma unroll
            for (int mt = 0; mt < 8; mt++)
                acc[mt][0] = acc[mt][1] = acc[mt][2] = acc[mt][3] = 0.f;

            #pragma unroll
            for (int kt = 0; kt < 11; kt++) {
                uint32_t bk = bbase + (uint32_t)(kt * 16 * BSTR);
                #pragma unroll
                for (int mt2 = 0; mt2 < 4; mt2++) {
                    uint32_t bh[4];
                    ldsm_x4t(bh, bk + mt2 * 32);
                    mma_f16(acc[2 * mt2],     a_frag[kt], bh[0], bh[1]);
                    mma_f16(acc[2 * mt2 + 1], a_frag[kt], bh[2], bh[3]);
                }
            }
            float* orow = out + (size_t)row * NROW;
            if (j1 < KDIM) {
                float* o1 = orow + j1 * MDIM + eq * 2;
                #pragma unroll
                for (int mt = 0; mt < 8; mt++)
                    *(float2*)(o1 + mt * 8) = make_float2(acc[mt][0], acc[mt][1]);
            }
            if (j2 < KDIM) {
                float* o2 = orow + j2 * MDIM + eq * 2;
                #pragma unroll
                for (int mt = 0; mt < 8; mt++)
                    *(float2*)(o2 + mt * 8) = make_float2(acc[mt][2], acc[mt][3]);
            }
            // -- butterfly own chunks of next row from prefetched regs --
            if (have_nxt) {
                #pragma unroll
                for (int t = 0; t < 14; t++)
                    bfly_store(pf[t], bnext, warp + 11 * t, lane, scale);
            }
        } else if (have_nxt) {
            // -------- helper warp: 18 contiguous chunks of next row --------
            const float* xn = x + (size_t)nxt * NROW;
            float2 pf[18];
            #pragma unroll
            for (int t = 0; t < 18; t++)
                pf[t] = *(const float2*)(xn + ((154 + t) << 6) + 2 * lane);
            #pragma unroll
            for (int t = 0; t < 18; t++)
                bfly_store(pf[t], bnext, 154 + t, lane, scale);
        }
        buf ^= 1;
        __syncthreads();
    }
}

extern "C" void kernel_launch(void* const* d_in, const int* in_sizes, int n_in,
                              void* d_out, int out_size) {
    const float* x   = (const float*)d_in[0];
    const float* had = (const float*)d_in[1];
    float* out = (float*)d_out;
    int rows = in_sizes[0] / NROW;

    cudaFuncSetAttribute(onl_had_r7_kernel,
                         cudaFuncAttributeMaxDynamicSharedMemorySize, SMEM_DYN);
    int grid = rows < 152 ? rows : 152;
    onl_had_r7_kernel<<<grid, NT, SMEM_DYN>>>(x, had, out, rows);
}